// round 2
// baseline (speedup 1.0000x reference)
#include <cuda_runtime.h>

#define BATCH    8
#define TLEN     16384
#define CH       32
#define NB       6
#define NTHREADS 576
#define HALO     63
#define T_TILE   (NTHREADS - 2*HALO)              /* 450 */
#define NTILES   ((TLEN + T_TILE - 1) / T_TILE)   /* 37  */
#define HBSTRIDE 33
#define HB_FLOATS (NTHREADS * HBSTRIDE)           /* 19008 */
#define NWARPS   (NTHREADS / 32)                  /* 18 */
#define W_FLOATS (3*CH*CH + 3*CH*CH + CH*CH + 3*CH)  /* 7264 */
#define SMEM_FLOATS (HB_FLOATS + W_FLOATS + 2*NWARPS)
#define SMEM_BYTES  (SMEM_FLOATS * 4)

__device__ float g_partials[BATCH * NTILES * 2];

__device__ __forceinline__ float sigm_(float x) {
    return 1.0f / (1.0f + __expf(-x));
}
__device__ __forceinline__ float tanh_(float x) {
    float e = __expf(2.0f * x);
    return 1.0f - 2.0f / (e + 1.0f);
}
__device__ __forceinline__ void fma4(float* acc, float4 w, float v) {
    acc[0] = fmaf(w.x, v, acc[0]);
    acc[1] = fmaf(w.y, v, acc[1]);
    acc[2] = fmaf(w.z, v, acc[2]);
    acc[3] = fmaf(w.w, v, acc[3]);
}

__global__ void __launch_bounds__(NTHREADS, 1)
wavenet_kernel(const float* __restrict__ x,
               const float* __restrict__ w_init,  const float* __restrict__ b_init,
               const float* __restrict__ w_tanh,  const float* __restrict__ b_tanh,
               const float* __restrict__ w_sig,   const float* __restrict__ b_sig,
               const float* __restrict__ w_skip,  const float* __restrict__ b_skip,
               const float* __restrict__ w_final, const float* __restrict__ b_final,
               const float* __restrict__ w_dense)
{
    extern __shared__ float smem[];
    float* hb   = smem;                    // [NTHREADS][33]
    float* swt  = smem + HB_FLOATS;        // 3*32*32
    float* sws  = swt + 3*CH*CH;           // 3*32*32
    float* swk  = sws + 3*CH*CH;           // 32*32
    float* sbt  = swk + CH*CH;             // 32
    float* sbs  = sbt + CH;                // 32
    float* sbk  = sbs + CH;                // 32
    float* sred = sbk + CH;                // 2*NWARPS

    const int tid  = threadIdx.x;
    const int bidx = blockIdx.x;
    const int b    = bidx / NTILES;
    const int tile = bidx - b * NTILES;
    const int t0   = tile * T_TILE;
    const int tg   = t0 - HALO + tid;
    const bool in_seq = (tg >= 0) && (tg < TLEN);

    const float xv = in_seq ? x[(size_t)b * TLEN + tg] : 0.0f;

    // ---- initial 1x1 conv: h = relu(x * w_init + b_init), zero outside sequence ----
    #pragma unroll
    for (int c = 0; c < CH; ++c) {
        float h = in_seq ? fmaxf(fmaf(xv, __ldg(&w_init[c]), __ldg(&b_init[c])), 0.0f) : 0.0f;
        hb[tid * HBSTRIDE + c] = h;
    }

    float at[CH], ag[CH];

    // ---- 6 residual blocks, all in shared memory ----
    for (int blk = 0; blk < NB; ++blk) {
        // cooperative weight load for this block
        {
            const float4* g = (const float4*)(w_tanh + blk * 3*CH*CH);
            float4* s = (float4*)swt;
            for (int j = tid; j < 768; j += NTHREADS) s[j] = g[j];
            g = (const float4*)(w_sig + blk * 3*CH*CH);
            s = (float4*)sws;
            for (int j = tid; j < 768; j += NTHREADS) s[j] = g[j];
            g = (const float4*)(w_skip + blk * CH*CH);
            s = (float4*)swk;
            for (int j = tid; j < 256; j += NTHREADS) s[j] = g[j];
            if (tid < CH) {
                sbt[tid] = b_tanh[blk*CH + tid];
                sbs[tid] = b_sig [blk*CH + tid];
                sbk[tid] = b_skip[blk*CH + tid];
            }
        }
        __syncthreads();   // weights ready + hb writes from prev iter visible

        const int d = 1 << blk;
        int pm = tid - d; if (pm < 0) pm = 0;
        int pp = tid + d; if (pp > NTHREADS - 1) pp = NTHREADS - 1;

        const float* hrm = hb + pm  * HBSTRIDE;
        const float* hr0 = hb + tid * HBSTRIDE;
        const float* hrp = hb + pp  * HBSTRIDE;

        #pragma unroll
        for (int c = 0; c < CH; ++c) { at[c] = sbt[c]; ag[c] = sbs[c]; }

        // dilated 3-tap convs (tanh branch + sigmoid branch)
        #pragma unroll 1
        for (int ci = 0; ci < CH; ++ci) {
            const float hm = hrm[ci], h0 = hr0[ci], hp = hrp[ci];
            const float4* wt0 = (const float4*)(swt +         ci*CH);
            const float4* wt1 = (const float4*)(swt + 1024 +  ci*CH);
            const float4* wt2 = (const float4*)(swt + 2048 +  ci*CH);
            const float4* vs0 = (const float4*)(sws +         ci*CH);
            const float4* vs1 = (const float4*)(sws + 1024 +  ci*CH);
            const float4* vs2 = (const float4*)(sws + 2048 +  ci*CH);
            #pragma unroll
            for (int q = 0; q < 8; ++q) {
                fma4(at + 4*q, wt0[q], hm);
                fma4(at + 4*q, wt1[q], h0);
                fma4(at + 4*q, wt2[q], hp);
                fma4(ag + 4*q, vs0[q], hm);
                fma4(ag + 4*q, vs1[q], h0);
                fma4(ag + 4*q, vs2[q], hp);
            }
        }

        // gated activation -> small local array (dynamic-indexed below)
        float gated[CH];
        #pragma unroll
        for (int c = 0; c < CH; ++c) gated[c] = tanh_(at[c]) * sigm_(ag[c]);

        // 1x1 skip conv
        #pragma unroll
        for (int c = 0; c < CH; ++c) ag[c] = sbk[c];
        #pragma unroll 1
        for (int ci = 0; ci < CH; ++ci) {
            const float g = gated[ci];
            const float4* wk = (const float4*)(swk + ci*CH);
            #pragma unroll
            for (int q = 0; q < 8; ++q) fma4(ag + 4*q, wk[q], g);
        }

        // residual: h_new = h_old + relu(skip)
        #pragma unroll
        for (int c = 0; c < CH; ++c) ag[c] = hr0[c] + fmaxf(ag[c], 0.0f);

        __syncthreads();   // everyone done reading old h
        #pragma unroll
        for (int c = 0; c < CH; ++c) hb[tid * HBSTRIDE + c] = in_seq ? ag[c] : 0.0f;
        // next iteration's leading __syncthreads() makes these writes visible
    }

    // ---- tail: skip_sum = h_final - h_init ; relu ; final 1x1 conv ; dense partial ----
    {
        const float4* g = (const float4*)w_final;
        float4* s = (float4*)swt;
        for (int j = tid; j < 256; j += NTHREADS) s[j] = g[j];
        if (tid < CH) {
            sbt[tid] = b_final[tid];
            sbs[tid] = w_init[tid];
            sbk[tid] = b_init[tid];
        }
    }
    __syncthreads();

    float l0 = 0.0f, l1 = 0.0f;
    const bool valid = (tid >= HALO) && (tid < HALO + T_TILE) && (tg < TLEN);
    if (valid) {
        float y1[CH];
        #pragma unroll
        for (int c = 0; c < CH; ++c) {
            float hinit = fmaxf(fmaf(xv, sbs[c], sbk[c]), 0.0f);
            float ss = hb[tid * HBSTRIDE + c] - hinit;   // skip_sum
            y1[c] = fmaxf(ss, 0.0f);                     // relu(skip_sum)
        }
        #pragma unroll
        for (int c = 0; c < CH; ++c) at[c] = sbt[c];
        #pragma unroll 1
        for (int ci = 0; ci < CH; ++ci) {
            const float g = y1[ci];
            const float4* wf = (const float4*)(swt + ci*CH);
            #pragma unroll
            for (int q = 0; q < 8; ++q) fma4(at + 4*q, wf[q], g);
        }
        const float2* wd = (const float2*)w_dense + (size_t)tg * CH;
        #pragma unroll
        for (int c = 0; c < CH; ++c) {
            float yv = fmaxf(at[c], 0.0f);               // relu(final conv)
            float2 w = __ldg(&wd[c]);
            l0 = fmaf(yv, w.x, l0);
            l1 = fmaf(yv, w.y, l1);
        }
    }

    // deterministic CTA reduction
    #pragma unroll
    for (int off = 16; off > 0; off >>= 1) {
        l0 += __shfl_down_sync(0xffffffffu, l0, off);
        l1 += __shfl_down_sync(0xffffffffu, l1, off);
    }
    const int wid = tid >> 5, lane = tid & 31;
    if (lane == 0) { sred[wid*2] = l0; sred[wid*2 + 1] = l1; }
    __syncthreads();
    if (tid == 0) {
        float s0 = 0.0f, s1 = 0.0f;
        #pragma unroll
        for (int w = 0; w < NWARPS; ++w) { s0 += sred[w*2]; s1 += sred[w*2 + 1]; }
        g_partials[(b * NTILES + tile) * 2 + 0] = s0;
        g_partials[(b * NTILES + tile) * 2 + 1] = s1;
    }
}

__global__ void finalize_kernel(const float* __restrict__ b_dense, float* __restrict__ out)
{
    int b = threadIdx.x;
    if (b < BATCH) {
        float s0 = b_dense[0], s1 = b_dense[1];
        for (int t = 0; t < NTILES; ++t) {
            s0 += g_partials[(b * NTILES + t) * 2 + 0];
            s1 += g_partials[(b * NTILES + t) * 2 + 1];
        }
        float m  = fmaxf(s0, s1);
        float e0 = expf(s0 - m), e1 = expf(s1 - m);
        float inv = 1.0f / (e0 + e1);
        out[b*2 + 0] = e0 * inv;
        out[b*2 + 1] = e1 * inv;
    }
}

extern "C" void kernel_launch(void* const* d_in, const int* in_sizes, int n_in,
                              void* d_out, int out_size)
{
    const float* x       = (const float*)d_in[0];
    const float* w_init  = (const float*)d_in[1];
    const float* b_init  = (const float*)d_in[2];
    const float* w_tanh  = (const float*)d_in[3];
    const float* b_tanh  = (const float*)d_in[4];
    const float* w_sig   = (const float*)d_in[5];
    const float* b_sig   = (const float*)d_in[6];
    const float* w_skip  = (const float*)d_in[7];
    const float* b_skip  = (const float*)d_in[8];
    const float* w_final = (const float*)d_in[9];
    const float* b_final = (const float*)d_in[10];
    const float* w_dense = (const float*)d_in[11];
    const float* b_dense = (const float*)d_in[12];

    cudaFuncSetAttribute(wavenet_kernel,
                         cudaFuncAttributeMaxDynamicSharedMemorySize, SMEM_BYTES);

    wavenet_kernel<<<BATCH * NTILES, NTHREADS, SMEM_BYTES>>>(
        x, w_init, b_init, w_tanh, b_tanh, w_sig, b_sig,
        w_skip, b_skip, w_final, b_final, w_dense);

    finalize_kernel<<<1, 32>>>(b_dense, (float*)d_out);
}

// round 4
// speedup vs baseline: 1.5403x; 1.5403x over previous
#include <cuda_runtime.h>

typedef unsigned long long ull;

#define BATCH   8
#define TLEN    16384
#define CH      32
#define NB      6
#define NT      544
#define NWARPS  17
#define HALO    63
#define SLOTS   1088            /* 2 slots per thread */
#define SROW    1088
#define T_TILE  962             /* SLOTS - 2*HALO */
#define NTILES  18              /* 18*962 = 17316 >= 16384 */
#define NCTAS   (BATCH*NTILES)  /* 144 */

#define BUFSZ     7264          /* gate 6144 + skip 1024 + 3x32 biases */
#define OFF_HB    0
#define OFF_BUF0  (CH*SROW)             /* 34816 */
#define OFF_BUF1  (OFF_BUF0 + BUFSZ)    /* 42080 */
#define OFF_WF    (OFF_BUF1 + BUFSZ)    /* 49344 */
#define OFF_BFIN  (OFF_WF + 1024)       /* 50368 */
#define OFF_RED   (OFF_BFIN + 32)       /* 50400 */
#define SMEM_FLOATS (OFF_RED + 2*NWARPS)
#define SMEM_BYTES  (SMEM_FLOATS*4)     /* ~201.7 KB */

/* in-buffer float offsets */
#define B_WT 0
#define B_WS 3072
#define B_WK 6144
#define B_BT 7168
#define B_BS 7200
#define B_BK 7232

__device__ float g_partials[NCTAS*2];

__device__ __forceinline__ void fma2(ull& d, ull a, ull b){
    asm("fma.rn.f32x2 %0, %1, %2, %0;" : "+l"(d) : "l"(a), "l"(b));
}
__device__ __forceinline__ ull pack2(float lo, float hi){
    ull r; asm("mov.b64 %0, {%1, %2};" : "=l"(r) : "f"(lo), "f"(hi)); return r;
}
__device__ __forceinline__ ull packdup(float v){ return pack2(v, v); }
__device__ __forceinline__ void unpack2(ull v, float& lo, float& hi){
    asm("mov.b64 {%0, %1}, %2;" : "=f"(lo), "=f"(hi) : "l"(v));
}
__device__ __forceinline__ float ex2_(float x){
    float y; asm("ex2.approx.f32 %0, %1;" : "=f"(y) : "f"(x)); return y;
}
__device__ __forceinline__ float rcp_(float x){
    float y; asm("rcp.approx.f32 %0, %1;" : "=f"(y) : "f"(x)); return y;
}
/* tanh(a)*sigmoid(g) = (e1-1)*e2 / ((e1+1)(e2+1)), e1=e^{2a}, e2=e^{g}; clamps keep exp finite */
__device__ __forceinline__ float gateval(float a, float g){
    a = fminf(fmaxf(a, -15.f), 15.f);
    g = fminf(fmaxf(g, -30.f), 30.f);
    float e1 = ex2_(a * 2.8853900817779268f);
    float e2 = ex2_(g * 1.4426950408889634f);
    return (e1 - 1.f) * e2 * rcp_((e1 + 1.f) * (e2 + 1.f));
}

__device__ __forceinline__ void copyw(float* dst,
    const float* wt, const float* ws, const float* wk,
    const float* bt, const float* bs, const float* bk, int blk, int tid)
{
    const float4* g1 = (const float4*)(wt + blk*3072);
    const float4* g2 = (const float4*)(ws + blk*3072);
    const float4* g3 = (const float4*)(wk + blk*1024);
    float4* d = (float4*)dst;
    for (int j = tid; j < 768; j += NT) d[j]        = g1[j];
    for (int j = tid; j < 768; j += NT) d[768 + j]  = g2[j];
    for (int j = tid; j < 256; j += NT) d[1536 + j] = g3[j];
    if (tid < 32){
        dst[B_BT + tid] = bt[blk*32 + tid];
        dst[B_BS + tid] = bs[blk*32 + tid];
        dst[B_BK + tid] = bk[blk*32 + tid];
    }
}

/* gate conv for 4 output channels (eighth e), both positions, weights shared */
__device__ __forceinline__ void conv4(const float* __restrict__ wt, const float* __restrict__ ws,
    const float* __restrict__ hb,
    int pmA, int s0A, int ppA, int pmB, int s0B, int ppB,
    ull bT0, ull bT1, ull bS0, ull bS1,
    ull& gA0, ull& gA1, ull& gB0, ull& gB1)
{
    ull tA0=bT0, tA1=bT1, uA0=bS0, uA1=bS1;
    ull tB0=bT0, tB1=bT1, uB0=bS0, uB1=bS1;
    #pragma unroll 2
    for (int ci = 0; ci < CH; ++ci){
        const float* hr = hb + ci*SROW;
        ull hmA = packdup(hr[pmA]), h0A = packdup(hr[s0A]), hpA = packdup(hr[ppA]);
        ull hmB = packdup(hr[pmB]), h0B = packdup(hr[s0B]), hpB = packdup(hr[ppB]);
        const float* wtc = wt + ci*CH;
        const float* wsc = ws + ci*CH;
        ulonglong2 t0 = *(const ulonglong2*)(wtc);
        ulonglong2 t1 = *(const ulonglong2*)(wtc + 1024);
        ulonglong2 t2 = *(const ulonglong2*)(wtc + 2048);
        ulonglong2 v0 = *(const ulonglong2*)(wsc);
        ulonglong2 v1 = *(const ulonglong2*)(wsc + 1024);
        ulonglong2 v2 = *(const ulonglong2*)(wsc + 2048);
        fma2(tA0,t0.x,hmA); fma2(tA1,t0.y,hmA); fma2(tB0,t0.x,hmB); fma2(tB1,t0.y,hmB);
        fma2(tA0,t1.x,h0A); fma2(tA1,t1.y,h0A); fma2(tB0,t1.x,h0B); fma2(tB1,t1.y,h0B);
        fma2(tA0,t2.x,hpA); fma2(tA1,t2.y,hpA); fma2(tB0,t2.x,hpB); fma2(tB1,t2.y,hpB);
        fma2(uA0,v0.x,hmA); fma2(uA1,v0.y,hmA); fma2(uB0,v0.x,hmB); fma2(uB1,v0.y,hmB);
        fma2(uA0,v1.x,h0A); fma2(uA1,v1.y,h0A); fma2(uB0,v1.x,h0B); fma2(uB1,v1.y,h0B);
        fma2(uA0,v2.x,hpA); fma2(uA1,v2.y,hpA); fma2(uB0,v2.x,hpB); fma2(uB1,v2.y,hpB);
    }
    float a0,a1,g0,g1;
    unpack2(tA0,a0,a1); unpack2(uA0,g0,g1); gA0 = pack2(gateval(a0,g0), gateval(a1,g1));
    unpack2(tA1,a0,a1); unpack2(uA1,g0,g1); gA1 = pack2(gateval(a0,g0), gateval(a1,g1));
    unpack2(tB0,a0,a1); unpack2(uB0,g0,g1); gB0 = pack2(gateval(a0,g0), gateval(a1,g1));
    unpack2(tB1,a0,a1); unpack2(uB1,g0,g1); gB1 = pack2(gateval(a0,g0), gateval(a1,g1));
}

/* 1x1 skip conv + residual h update for one slot */
__device__ __forceinline__ void skip_pos(const float* __restrict__ wk, const float* __restrict__ bk,
    const ull* __restrict__ gated, float* __restrict__ hb, int s, bool in_seq)
{
    ull acc[16];
    #pragma unroll
    for (int k = 0; k < 16; ++k) acc[k] = pack2(bk[2*k], bk[2*k+1]);
    #pragma unroll
    for (int p = 0; p < 16; ++p){
        float g0, g1; unpack2(gated[p], g0, g1);
        ull pg0 = packdup(g0), pg1 = packdup(g1);
        const ulonglong2* W0 = (const ulonglong2*)(wk + (2*p)*CH);
        const ulonglong2* W1 = (const ulonglong2*)(wk + (2*p+1)*CH);
        #pragma unroll
        for (int q = 0; q < 8; ++q){            /* FIX: 8 x ulonglong2 = 32 out channels */
            ulonglong2 w = W0[q];
            fma2(acc[2*q], w.x, pg0); fma2(acc[2*q+1], w.y, pg0);
            w = W1[q];
            fma2(acc[2*q], w.x, pg1); fma2(acc[2*q+1], w.y, pg1);
        }
    }
    #pragma unroll
    for (int k = 0; k < 16; ++k){
        float s0, s1; unpack2(acc[k], s0, s1);
        float* r0 = hb + (2*k)*SROW + s;
        float* r1 = hb + (2*k+1)*SROW + s;
        float n0 = in_seq ? (*r0 + fmaxf(s0, 0.f)) : 0.f;
        float n1 = in_seq ? (*r1 + fmaxf(s1, 0.f)) : 0.f;
        *r0 = n0; *r1 = n1;
    }
}

/* tail for one valid slot: skip_sum = h - h_init ; relu ; final 1x1 ; relu ; dense dot */
__device__ __forceinline__ void tail_slot(const float* __restrict__ sm, int s, int tg, float xv,
    const float* __restrict__ w_init, const float* __restrict__ b_init,
    const float* __restrict__ w_dense, float& l0, float& l1)
{
    ull F[16];
    const float* bf = sm + OFF_BFIN;
    #pragma unroll
    for (int k = 0; k < 16; ++k) F[k] = pack2(bf[2*k], bf[2*k+1]);
    #pragma unroll 4
    for (int ci = 0; ci < CH; ++ci){
        float hi0 = fmaxf(fmaf(xv, __ldg(w_init + ci), __ldg(b_init + ci)), 0.f);
        float y   = fmaxf(sm[OFF_HB + ci*SROW + s] - hi0, 0.f);
        ull py = packdup(y);
        const ulonglong2* Wf = (const ulonglong2*)(sm + OFF_WF + ci*CH);
        #pragma unroll
        for (int q = 0; q < 8; ++q){            /* FIX: 8 x ulonglong2 = 32 out channels */
            ulonglong2 w = Wf[q];
            fma2(F[2*q], w.x, py); fma2(F[2*q+1], w.y, py);
        }
    }
    const float4* wd4 = (const float4*)(w_dense + (size_t)tg * (CH*2));
    #pragma unroll
    for (int k = 0; k < 16; ++k){
        float ya, yb; unpack2(F[k], ya, yb);
        ya = fmaxf(ya, 0.f); yb = fmaxf(yb, 0.f);
        float4 wv = __ldg(wd4 + k);
        l0 = fmaf(ya, wv.x, fmaf(yb, wv.z, l0));
        l1 = fmaf(ya, wv.y, fmaf(yb, wv.w, l1));
    }
}

__global__ void __launch_bounds__(NT, 1)
wavenet_kernel(const float* __restrict__ x,
               const float* __restrict__ w_init,  const float* __restrict__ b_init,
               const float* __restrict__ w_tanh,  const float* __restrict__ b_tanh,
               const float* __restrict__ w_sig,   const float* __restrict__ b_sig,
               const float* __restrict__ w_skip,  const float* __restrict__ b_skip,
               const float* __restrict__ w_final, const float* __restrict__ b_final,
               const float* __restrict__ w_dense)
{
    extern __shared__ float sm[];
    float* hb = sm + OFF_HB;
    const int tid  = threadIdx.x;
    const int b    = blockIdx.x / NTILES;
    const int tile = blockIdx.x - b*NTILES;
    const int t0   = tile * T_TILE;

    const int sA = tid, sB = tid + NT;
    const int tgA = t0 - HALO + sA;
    const int tgB = t0 - HALO + sB;
    const bool inA = (tgA >= 0) && (tgA < TLEN);
    const bool inB = (tgB >= 0) && (tgB < TLEN);
    const float xA = inA ? x[(size_t)b*TLEN + tgA] : 0.f;
    const float xB = inB ? x[(size_t)b*TLEN + tgB] : 0.f;

    /* preload block-0 weights, final weights, final bias */
    copyw(sm + OFF_BUF0, w_tanh, w_sig, w_skip, b_tanh, b_sig, b_skip, 0, tid);
    {
        const float4* gf = (const float4*)w_final;
        float4* f4 = (float4*)(sm + OFF_WF);
        for (int j = tid; j < 256; j += NT) f4[j] = gf[j];
        if (tid < 32) sm[OFF_BFIN + tid] = b_final[tid];
    }
    /* initial h = relu(x*w_init + b_init), transposed [c][slot], zero outside sequence */
    #pragma unroll 4
    for (int c = 0; c < CH; ++c){
        float wi = __ldg(w_init + c), bi = __ldg(b_init + c);
        hb[c*SROW + sA] = inA ? fmaxf(fmaf(xA, wi, bi), 0.f) : 0.f;
        hb[c*SROW + sB] = inB ? fmaxf(fmaf(xB, wi, bi), 0.f) : 0.f;
    }

    ull gA[16], gB[16];

    #pragma unroll 1
    for (int blk = 0; blk < NB; ++blk){
        __syncthreads();   /* SA: weights for blk + h writes visible */
        const float* buf = sm + OFF_BUF0 + (blk & 1)*BUFSZ;
        if (blk + 1 < NB)  /* prefetch next block's weights into the other buffer */
            copyw(sm + OFF_BUF0 + ((blk+1) & 1)*BUFSZ,
                  w_tanh, w_sig, w_skip, b_tanh, b_sig, b_skip, blk+1, tid);

        const int d = 1 << blk;
        int pmA = sA - d; if (pmA < 0) pmA = 0;
        int ppA = sA + d; if (ppA > SLOTS-1) ppA = SLOTS-1;
        int pmB = sB - d; if (pmB < 0) pmB = 0;
        int ppB = sB + d; if (ppB > SLOTS-1) ppB = SLOTS-1;

        const float* bt = buf + B_BT;
        const float* bs = buf + B_BS;
        #pragma unroll
        for (int e = 0; e < 8; ++e){
            ull bT0 = pack2(bt[4*e], bt[4*e+1]), bT1 = pack2(bt[4*e+2], bt[4*e+3]);
            ull bS0 = pack2(bs[4*e], bs[4*e+1]), bS1 = pack2(bs[4*e+2], bs[4*e+3]);
            conv4(buf + B_WT + 4*e, buf + B_WS + 4*e, hb,
                  pmA, sA, ppA, pmB, sB, ppB,
                  bT0, bT1, bS0, bS1,
                  gA[2*e], gA[2*e+1], gB[2*e], gB[2*e+1]);
        }
        __syncthreads();   /* SB: all h reads done */
        skip_pos(buf + B_WK, buf + B_BK, gA, hb, sA, inA);
        skip_pos(buf + B_WK, buf + B_BK, gB, hb, sB, inB);
    }

    /* tail: only own slots read -> no extra sync needed */
    float l0 = 0.f, l1 = 0.f;
    if (sA >= HALO && sA < HALO + T_TILE && tgA < TLEN)
        tail_slot(sm, sA, tgA, xA, w_init, b_init, w_dense, l0, l1);
    if (sB >= HALO && sB < HALO + T_TILE && tgB < TLEN)
        tail_slot(sm, sB, tgB, xB, w_init, b_init, w_dense, l0, l1);

    #pragma unroll
    for (int off = 16; off > 0; off >>= 1){
        l0 += __shfl_down_sync(0xffffffffu, l0, off);
        l1 += __shfl_down_sync(0xffffffffu, l1, off);
    }
    const int wid = tid >> 5, lane = tid & 31;
    float* sred = sm + OFF_RED;
    if (lane == 0){ sred[wid*2] = l0; sred[wid*2+1] = l1; }
    __syncthreads();
    if (tid == 0){
        float s0 = 0.f, s1 = 0.f;
        #pragma unroll
        for (int w = 0; w < NWARPS; ++w){ s0 += sred[w*2]; s1 += sred[w*2+1]; }
        g_partials[blockIdx.x*2 + 0] = s0;
        g_partials[blockIdx.x*2 + 1] = s1;
    }
}

__global__ void finalize_kernel(const float* __restrict__ b_dense, float* __restrict__ out)
{
    int b = threadIdx.x;
    if (b < BATCH){
        float s0 = b_dense[0], s1 = b_dense[1];
        for (int t = 0; t < NTILES; ++t){
            s0 += g_partials[(b*NTILES + t)*2 + 0];
            s1 += g_partials[(b*NTILES + t)*2 + 1];
        }
        float m = fmaxf(s0, s1);
        float e0 = expf(s0 - m), e1 = expf(s1 - m);
        float inv = 1.f / (e0 + e1);
        out[b*2 + 0] = e0*inv;
        out[b*2 + 1] = e1*inv;
    }
}

extern "C" void kernel_launch(void* const* d_in, const int* in_sizes, int n_in,
                              void* d_out, int out_size)
{
    const float* x       = (const float*)d_in[0];
    const float* w_init  = (const float*)d_in[1];
    const float* b_init  = (const float*)d_in[2];
    const float* w_tanh  = (const float*)d_in[3];
    const float* b_tanh  = (const float*)d_in[4];
    const float* w_sig   = (const float*)d_in[5];
    const float* b_sig   = (const float*)d_in[6];
    const float* w_skip  = (const float*)d_in[7];
    const float* b_skip  = (const float*)d_in[8];
    const float* w_final = (const float*)d_in[9];
    const float* b_final = (const float*)d_in[10];
    const float* w_dense = (const float*)d_in[11];
    const float* b_dense = (const float*)d_in[12];

    cudaFuncSetAttribute(wavenet_kernel,
                         cudaFuncAttributeMaxDynamicSharedMemorySize, SMEM_BYTES);

    wavenet_kernel<<<NCTAS, NT, SMEM_BYTES>>>(
        x, w_init, b_init, w_tanh, b_tanh, w_sig, b_sig,
        w_skip, b_skip, w_final, b_final, w_dense);

    finalize_kernel<<<1, 32>>>(b_dense, (float*)d_out);
}